// round 1
// baseline (speedup 1.0000x reference)
#include <cuda_runtime.h>
#include <math.h>

// Problem constants
#define BATCH 64
#define CH    32
#define HH    128
#define WW    128
#define EPSV  1e-5f

// Scratch for the intermediate h = conv1(relu(bn1(x))) + b1  (128 MB, static — no allocs)
__device__ float g_h[(size_t)BATCH * CH * HH * WW];

// Tile geometry: 8x8 output pixels per block, 4 cout-groups of 8 couts -> 256 threads
#define TILE      8
#define IN_TILE   10           // 8 + 2 halo
#define W_SMEM    (CH * CH * 9)        // 9216 floats, layout [cin][tap][cout]
#define IN_SMEM   (CH * IN_TILE * IN_TILE) // 3200 floats, layout [cin][iy][ix]

// smem floats total: 9216 + 3200 + 64 = 12480 -> 49920 bytes (dynamic)
#define SMEM_BYTES ((W_SMEM + IN_SMEM + 2 * CH) * sizeof(float))

template <bool RESIDUAL>
__global__ void bnrelu_conv3x3_kernel(
    const float* __restrict__ src,    // pre-BN input, NCHW
    const float* __restrict__ gamma,
    const float* __restrict__ beta,
    const float* __restrict__ mean,
    const float* __restrict__ var,
    const float* __restrict__ w,      // OIHW [32][32][3][3]
    const float* __restrict__ bias,   // [32]
    const float* __restrict__ resid,  // residual (x) or nullptr
    float* __restrict__ dst)
{
    extern __shared__ float smem[];
    float* w_s     = smem;                  // [ (cin*9+tap)*32 + cout ]
    float* in_s    = smem + W_SMEM;         // [ cin*100 + iy*10 + ix ]
    float* scale_s = in_s + IN_SMEM;        // [32]
    float* shift_s = scale_s + CH;          // [32]

    const int tid  = threadIdx.x;
    const int b    = blockIdx.y;
    const int tile = blockIdx.x;            // 0..255 (16x16 tiles of 8x8)
    const int ox   = (tile & 15) * TILE;
    const int oy   = (tile >> 4) * TILE;

    // BN scale/shift per channel
    if (tid < CH) {
        float sc = gamma[tid] * rsqrtf(var[tid] + EPSV);
        scale_s[tid] = sc;
        shift_s[tid] = beta[tid] - mean[tid] * sc;
    }

    // Stage weights transposed: w_s[(cin*9+tap)*32 + cout] = w[cout*288 + cin*9 + tap]
    for (int i = tid; i < W_SMEM; i += 256) {
        int co = i / 288;
        int r  = i - co * 288;              // cin*9 + tap
        w_s[r * 32 + co] = w[i];
    }
    __syncthreads();                        // scale_s ready for input staging

    // Stage activated input halo tile: relu(bn(src)), zero-padded
    const float* srcb = src + (size_t)b * CH * HH * WW;
    for (int i = tid; i < IN_SMEM; i += 256) {
        int ci = i / (IN_TILE * IN_TILE);
        int p  = i - ci * (IN_TILE * IN_TILE);
        int iy = p / IN_TILE;
        int ix = p - iy * IN_TILE;
        int gy = oy - 1 + iy;
        int gx = ox - 1 + ix;
        float v = 0.0f;
        if ((unsigned)gy < (unsigned)HH && (unsigned)gx < (unsigned)WW) {
            v = srcb[(ci * HH + gy) * WW + gx] * scale_s[ci] + shift_s[ci];
            v = fmaxf(v, 0.0f);
        }
        in_s[i] = v;
    }
    __syncthreads();

    // Thread mapping: group g (8 couts), pixel (ty,tx) in 8x8 tile.
    // Warps have a single g -> weight LDS.128 are warp-broadcast.
    const int g  = tid >> 6;                // 0..3
    const int p  = tid & 63;
    const int ty = p >> 3;
    const int tx = p & 7;

    float acc[8];
    #pragma unroll
    for (int j = 0; j < 8; j++) acc[j] = 0.0f;

    for (int ci = 0; ci < CH; ci++) {
        // 9 input values for this output pixel's receptive field
        float xv[9];
        const float* ip = in_s + ci * (IN_TILE * IN_TILE) + ty * IN_TILE + tx;
        #pragma unroll
        for (int ky = 0; ky < 3; ky++)
            #pragma unroll
            for (int kx = 0; kx < 3; kx++)
                xv[ky * 3 + kx] = ip[ky * IN_TILE + kx];

        #pragma unroll
        for (int t = 0; t < 9; t++) {
            const float4* wp = (const float4*)(w_s + (ci * 9 + t) * 32 + (g << 3));
            float4 wa = wp[0];
            float4 wb = wp[1];
            float  xx = xv[t];
            acc[0] = fmaf(xx, wa.x, acc[0]);
            acc[1] = fmaf(xx, wa.y, acc[1]);
            acc[2] = fmaf(xx, wa.z, acc[2]);
            acc[3] = fmaf(xx, wa.w, acc[3]);
            acc[4] = fmaf(xx, wb.x, acc[4]);
            acc[5] = fmaf(xx, wb.y, acc[5]);
            acc[6] = fmaf(xx, wb.z, acc[6]);
            acc[7] = fmaf(xx, wb.w, acc[7]);
        }
    }

    // Epilogue: bias (+ residual), write NCHW
    const int gy = oy + ty;
    const int gx = ox + tx;
    float*       dstb = dst + (size_t)b * CH * HH * WW;
    const float* rb   = RESIDUAL ? (resid + (size_t)b * CH * HH * WW) : nullptr;

    #pragma unroll
    for (int j = 0; j < 8; j++) {
        int    co  = (g << 3) + j;
        size_t idx = ((size_t)co * HH + gy) * WW + gx;
        float  v   = acc[j] + bias[co];
        if (RESIDUAL) v += rb[idx];
        dstb[idx] = v;
    }
}

extern "C" void kernel_launch(void* const* d_in, const int* in_sizes, int n_in,
                              void* d_out, int out_size)
{
    const float* x         = (const float*)d_in[0];
    const float* bn1_gamma = (const float*)d_in[1];
    const float* bn1_beta  = (const float*)d_in[2];
    const float* bn1_mean  = (const float*)d_in[3];
    const float* bn1_var   = (const float*)d_in[4];
    const float* w1        = (const float*)d_in[5];
    const float* b1        = (const float*)d_in[6];
    const float* bn2_gamma = (const float*)d_in[7];
    const float* bn2_beta  = (const float*)d_in[8];
    const float* bn2_mean  = (const float*)d_in[9];
    const float* bn2_var   = (const float*)d_in[10];
    const float* w2        = (const float*)d_in[11];
    const float* b2        = (const float*)d_in[12];
    float* out = (float*)d_out;

    // scratch pointer (no alloc: static __device__ array)
    void* hptr = nullptr;
    cudaGetSymbolAddress(&hptr, g_h);
    float* h = (float*)hptr;

    cudaFuncSetAttribute(bnrelu_conv3x3_kernel<false>,
                         cudaFuncAttributeMaxDynamicSharedMemorySize, (int)SMEM_BYTES);
    cudaFuncSetAttribute(bnrelu_conv3x3_kernel<true>,
                         cudaFuncAttributeMaxDynamicSharedMemorySize, (int)SMEM_BYTES);

    dim3 grid((HH / TILE) * (WW / TILE), BATCH);   // (256, 64)
    dim3 block(256);

    bnrelu_conv3x3_kernel<false><<<grid, block, SMEM_BYTES>>>(
        x, bn1_gamma, bn1_beta, bn1_mean, bn1_var, w1, b1, nullptr, h);

    bnrelu_conv3x3_kernel<true><<<grid, block, SMEM_BYTES>>>(
        h, bn2_gamma, bn2_beta, bn2_mean, bn2_var, w2, b2, x, out);
}

// round 3
// speedup vs baseline: 5.1960x; 5.1960x over previous
#include <cuda_runtime.h>
#include <cstdint>
#include <math.h>

#define BATCH 64
#define CH    32
#define HH    128
#define WW    128
#define PAD   130
#define EPSV  1e-5f
#define RROWS 4

// Padded NHWC activation scratch, channels in K-permuted order; borders zero.
__device__ float g_a1[(size_t)BATCH * PAD * PAD * CH];
__device__ float g_a2[(size_t)BATCH * PAD * PAD * CH];

// ---- helpers ----
__device__ __forceinline__ uint32_t f2tf32(float f) {
    uint32_t u;
    asm("cvt.rna.tf32.f32 %0, %1;" : "=r"(u) : "f"(f));
    return u;
}
// K-permutation within each 8-chunk: k stored at pos 2*(k&3) + ((k>>2)&1)
__device__ __host__ __forceinline__ int posidx(int ci) {
    return (ci & 24) | ((ci & 3) << 1) | ((ci >> 2) & 1);
}

__device__ __forceinline__ void mma_tf32(float c[4],
                                         uint32_t a0, uint32_t a1, uint32_t a2, uint32_t a3,
                                         uint32_t b0, uint32_t b1) {
    asm volatile(
        "mma.sync.aligned.m16n8k8.row.col.f32.tf32.tf32.f32 "
        "{%0,%1,%2,%3}, {%4,%5,%6,%7}, {%8,%9}, {%0,%1,%2,%3};"
        : "+f"(c[0]), "+f"(c[1]), "+f"(c[2]), "+f"(c[3])
        : "r"(a0), "r"(a1), "r"(a2), "r"(a3), "r"(b0), "r"(b1));
}

// ---- prep: x NCHW -> relu(bn1(x)) padded NHWC (permuted channels); zero borders ----
__global__ void prep_kernel(const float* __restrict__ x,
                            const float* __restrict__ gamma, const float* __restrict__ beta,
                            const float* __restrict__ mean,  const float* __restrict__ var)
{
    __shared__ float s1[CH], t1[CH];
    int tid = threadIdx.x;
    if (tid < CH) {
        float sc = gamma[tid] * rsqrtf(var[tid] + EPSV);
        s1[tid] = sc;
        t1[tid] = beta[tid] - mean[tid] * sc;
    }
    __syncthreads();
    size_t t = (size_t)blockIdx.x * blockDim.x + tid;
    if (t >= (size_t)BATCH * PAD * PAD) return;
    int xp  = (int)(t % PAD);
    int ypb = (int)(t / PAD);
    int yp  = ypb % PAD;
    int b   = ypb / PAD;

    float4* dst1 = (float4*)(g_a1 + t * CH);
    bool border = (xp == 0) | (xp == PAD - 1) | (yp == 0) | (yp == PAD - 1);
    if (border) {
        float4 z = make_float4(0.f, 0.f, 0.f, 0.f);
        float4* dst2 = (float4*)(g_a2 + t * CH);
        #pragma unroll
        for (int i = 0; i < 8; i++) { dst1[i] = z; dst2[i] = z; }
    } else {
        int y = yp - 1, xx = xp - 1;
        const float* xb = x + (size_t)b * CH * HH * WW + (size_t)y * WW + xx;
        float ov[CH];
        #pragma unroll
        for (int ci = 0; ci < CH; ci++) {
            float v = fmaxf(xb[(size_t)ci * HH * WW] * s1[ci] + t1[ci], 0.f);
            ov[posidx(ci)] = v;
        }
        #pragma unroll
        for (int i = 0; i < 8; i++)
            dst1[i] = make_float4(ov[4 * i], ov[4 * i + 1], ov[4 * i + 2], ov[4 * i + 3]);
    }
}

// ---- conv: tf32 mma.sync implicit GEMM ----
#define ASTRIDE 40                  // floats per pixel in smem (bank-conflict-free)
#define ASLOT   (PAD * ASTRIDE)     // 5200 floats per input row
#define ANF     (6 * ASLOT)         // 31200 floats
#define BNF     (9 * 4 * 32 * 8)    // 9216 floats
#define SNF     (ANF + BNF)
#define SMEMB   ((SNF + 64) * 4)    // + SS/TT

// MODE 0: conv1 -> epilogue (bias1, bn2, relu) -> g_a2 (padded NHWC, permuted)
// MODE 1: conv2 -> epilogue (bias2 + residual) -> NCHW out
template <int MODE>
__global__ void __launch_bounds__(256, 1)
conv_kernel(const float* __restrict__ src,   // padded NHWC, permuted channels
            const float* __restrict__ w,     // OIHW
            const float* __restrict__ bias,
            const float* __restrict__ g2, const float* __restrict__ be2,
            const float* __restrict__ m2, const float* __restrict__ v2,
            const float* __restrict__ resid,
            float* __restrict__ dst)
{
    extern __shared__ float sm[];
    float* As = sm;
    float* Bs = sm + ANF;
    float* SS = sm + SNF;
    float* TT = SS + 32;

    const int tid = threadIdx.x;
    const int b   = blockIdx.y;
    const int y0  = blockIdx.x * RROWS;

    if (MODE == 0 && tid < CH) {
        float sc = g2[tid] * rsqrtf(v2[tid] + EPSV);
        SS[tid] = sc;
        TT[tid] = bias[tid] * sc + (be2[tid] - m2[tid] * sc);
    }

    // Stage weights: Bs[((tap*4+q)*32 + co)*8 + pos] = tf32(w)
    for (int i = tid; i < CH * CH * 9; i += 256) {
        int co  = i / 288;
        int rem = i - co * 288;
        int ci  = rem / 9;
        int tap = rem - ci * 9;
        int q   = ci >> 3;
        int c   = ci & 7;
        int pos = ((c & 3) << 1) | ((c >> 2) & 1);
        Bs[((tap * 4 + q) * 32 + co) * 8 + pos] = __uint_as_float(f2tf32(w[i]));
    }

    // Stage 6 input rows (already channel-permuted in global), convert to tf32
    const float* srcb = src + ((size_t)b * PAD + y0) * (PAD * CH);
    for (int i = tid; i < 6 * 1040; i += 256) {          // 1040 float4 per row
        int s = i / 1040;
        int j = i - s * 1040;
        int xq = j >> 3;                                  // pixel
        int f4 = j & 7;
        float4 v = ((const float4*)(srcb + (size_t)s * (PAD * CH)))[j];
        uint4 tv;
        tv.x = f2tf32(v.x); tv.y = f2tf32(v.y); tv.z = f2tf32(v.z); tv.w = f2tf32(v.w);
        *(uint4*)(As + s * ASLOT + xq * ASTRIDE + f4 * 4) = tv;
    }
    __syncthreads();

    // Thread/warp mapping
    const int lane = tid & 31;
    const int warp = tid >> 5;
    const int g    = lane >> 2;       // 0..7
    const int tig  = lane & 3;        // 0..3
    const int r    = warp >> 1;       // output row within tile (0..3)
    const int x0   = (warp & 1) * 64; // half-row

    float C[4][4][4];
    #pragma unroll
    for (int mt = 0; mt < 4; mt++)
        #pragma unroll
        for (int n = 0; n < 4; n++)
            #pragma unroll
            for (int k = 0; k < 4; k++) C[mt][n][k] = 0.f;

    #pragma unroll 1
    for (int ky = 0; ky < 3; ky++) {
        #pragma unroll 1
        for (int kx = 0; kx < 3; kx++) {
            const int tap = ky * 3 + kx;
            // B fragments for this tap: [q][n][2]
            uint32_t bq[4][4][2];
            const float* Bt = Bs + tap * 1024;
            #pragma unroll
            for (int q = 0; q < 4; q++)
                #pragma unroll
                for (int n = 0; n < 4; n++) {
                    float2 bb = *(const float2*)(Bt + (q * 32 + n * 8 + g) * 8 + 2 * tig);
                    bq[q][n][0] = __float_as_uint(bb.x);
                    bq[q][n][1] = __float_as_uint(bb.y);
                }
            const float* Arow = As + (r + ky) * ASLOT + kx * ASTRIDE;
            #pragma unroll
            for (int mt = 0; mt < 4; mt++) {
                const int xb = x0 + mt * 16;
                #pragma unroll
                for (int q = 0; q < 4; q++) {
                    const float* ap = Arow + (xb + g) * ASTRIDE + q * 8 + 2 * tig;
                    float2 a01 = *(const float2*)ap;                    // rows g
                    float2 a23 = *(const float2*)(ap + 8 * ASTRIDE);    // rows g+8
                    uint32_t a0 = __float_as_uint(a01.x);
                    uint32_t a2 = __float_as_uint(a01.y);
                    uint32_t a1 = __float_as_uint(a23.x);
                    uint32_t a3 = __float_as_uint(a23.y);
                    #pragma unroll
                    for (int n = 0; n < 4; n++)
                        mma_tf32(C[mt][n], a0, a1, a2, a3, bq[q][n][0], bq[q][n][1]);
                }
            }
        }
    }

    // Epilogue. c0: (x=xb+g, co), c1: (x, co+1), c2: (x+8, co), c3: (x+8, co+1)
    const int y = y0 + r;
    #pragma unroll
    for (int mt = 0; mt < 4; mt++) {
        const int xb = x0 + mt * 16;
        #pragma unroll
        for (int n = 0; n < 4; n++) {
            const int co = n * 8 + 2 * tig;
            if (MODE == 0) {
                float s0 = SS[co],     t0 = TT[co];
                float s1 = SS[co + 1], t1 = TT[co + 1];
                float v0 = fmaxf(C[mt][n][0] * s0 + t0, 0.f);
                float v1 = fmaxf(C[mt][n][1] * s1 + t1, 0.f);
                float v2 = fmaxf(C[mt][n][2] * s0 + t0, 0.f);
                float v3 = fmaxf(C[mt][n][3] * s1 + t1, 0.f);
                size_t p0 = (((size_t)b * PAD + (y + 1)) * PAD + (xb + g + 1)) * CH;
                size_t p1 = p0 + 8 * CH;
                int c0p = posidx(co), c1p = posidx(co + 1);
                dst[p0 + c0p] = v0;
                dst[p0 + c1p] = v1;
                dst[p1 + c0p] = v2;
                dst[p1 + c1p] = v3;
            } else {
                float bb0 = bias[co], bb1 = bias[co + 1];
                size_t o00 = (((size_t)b * CH + co)     * HH + y) * WW + (xb + g);
                size_t o01 = (((size_t)b * CH + co + 1) * HH + y) * WW + (xb + g);
                dst[o00]     = C[mt][n][0] + bb0 + resid[o00];
                dst[o01]     = C[mt][n][1] + bb1 + resid[o01];
                dst[o00 + 8] = C[mt][n][2] + bb0 + resid[o00 + 8];
                dst[o01 + 8] = C[mt][n][3] + bb1 + resid[o01 + 8];
            }
        }
    }
}

// ---- launch ----
extern "C" void kernel_launch(void* const* d_in, const int* in_sizes, int n_in,
                              void* d_out, int out_size)
{
    const float* x         = (const float*)d_in[0];
    const float* bn1_gamma = (const float*)d_in[1];
    const float* bn1_beta  = (const float*)d_in[2];
    const float* bn1_mean  = (const float*)d_in[3];
    const float* bn1_var   = (const float*)d_in[4];
    const float* w1        = (const float*)d_in[5];
    const float* b1        = (const float*)d_in[6];
    const float* bn2_gamma = (const float*)d_in[7];
    const float* bn2_beta  = (const float*)d_in[8];
    const float* bn2_mean  = (const float*)d_in[9];
    const float* bn2_var   = (const float*)d_in[10];
    const float* w2        = (const float*)d_in[11];
    const float* b2        = (const float*)d_in[12];
    float* out = (float*)d_out;

    void *a1p = nullptr, *a2p = nullptr;
    cudaGetSymbolAddress(&a1p, g_a1);
    cudaGetSymbolAddress(&a2p, g_a2);
    float* a1 = (float*)a1p;
    float* a2 = (float*)a2p;

    cudaFuncSetAttribute(conv_kernel<0>, cudaFuncAttributeMaxDynamicSharedMemorySize, SMEMB);
    cudaFuncSetAttribute(conv_kernel<1>, cudaFuncAttributeMaxDynamicSharedMemorySize, SMEMB);

    {
        int total  = BATCH * PAD * PAD;
        int blocks = (total + 255) / 256;
        prep_kernel<<<blocks, 256>>>(x, bn1_gamma, bn1_beta, bn1_mean, bn1_var);
    }

    dim3 grid(HH / RROWS, BATCH);   // (32, 64)

    conv_kernel<0><<<grid, 256, SMEMB>>>(a1, w1, b1,
                                         bn2_gamma, bn2_beta, bn2_mean, bn2_var,
                                         nullptr, a2);

    conv_kernel<1><<<grid, 256, SMEMB>>>(a2, w2, b2,
                                         nullptr, nullptr, nullptr, nullptr,
                                         x, out);
}

// round 5
// speedup vs baseline: 5.5079x; 1.0600x over previous
#include <cuda_runtime.h>
#include <cstdint>
#include <math.h>

#define BATCH 64
#define CH    32
#define HH    128
#define WW    128
#define PAD   130
#define EPSV  1e-5f
#define RROWS 4
#define HW    (HH * WW)

// conv1 output activations: padded NHWC, K-permuted channels, tf32-quantized; borders zero
__device__ float g_a2[(size_t)BATCH * PAD * PAD * CH];

// ---- helpers ----
__device__ __forceinline__ uint32_t f2tf32(float f) {
    uint32_t u;
    asm("cvt.rna.tf32.f32 %0, %1;" : "=r"(u) : "f"(f));
    return u;
}
__device__ __host__ __forceinline__ int posidx(int ci) {
    return (ci & 24) | ((ci & 3) << 1) | ((ci >> 2) & 1);
}
__device__ __forceinline__ void mma_tf32(float c[4],
                                         uint32_t a0, uint32_t a1, uint32_t a2, uint32_t a3,
                                         uint32_t b0, uint32_t b1) {
    asm volatile(
        "mma.sync.aligned.m16n8k8.row.col.f32.tf32.tf32.f32 "
        "{%0,%1,%2,%3}, {%4,%5,%6,%7}, {%8,%9}, {%0,%1,%2,%3};"
        : "+f"(c[0]), "+f"(c[1]), "+f"(c[2]), "+f"(c[3])
        : "r"(a0), "r"(a1), "r"(a2), "r"(a3), "r"(b0), "r"(b1));
}

// ---- smem layout (floats) ----
#define ASTRIDE 40
#define ASLOT   (66 * ASTRIDE)        // 2640 floats per staged input row (66 px)
#define ANF     (6 * ASLOT)           // 15840
#define BNF     (9 * 4 * 32 * 8)      // 9216
#define OFF_SS1 (ANF + BNF)           // 25056
#define OFF_TT1 (OFF_SS1 + 32)
#define OFF_SS2 (OFF_TT1 + 32)
#define OFF_TT2 (OFF_SS2 + 32)
#define SNF     (OFF_TT2 + 32)        // 25184 floats
#define SMEMB   (SNF * 4)             // 100736 B -> 2 CTAs/SM
// epilogue staging (MODE 0) reuses As: 256 px * 33 = 8448 floats

// zero borders of g_a2 (516 border px per batch)
__global__ void border_kernel() {
    int i = blockIdx.x * 256 + threadIdx.x;     // i over 64*516*8 float4
    if (i >= BATCH * 516 * 8) return;
    int f4 = i & 7;
    int t  = i >> 3;
    int p  = t % 516;
    int b  = t / 516;
    int yp, xp;
    if      (p < 130) { yp = 0;       xp = p; }
    else if (p < 260) { yp = PAD - 1; xp = p - 130; }
    else if (p < 388) { yp = p - 259; xp = 0; }
    else              { yp = p - 387; xp = PAD - 1; }
    float4* d = (float4*)(g_a2 + (((size_t)b * PAD + yp) * PAD + xp) * CH);
    d[f4] = make_float4(0.f, 0.f, 0.f, 0.f);
}

// MODE 0: x NCHW --(bn1+relu staged)--> conv1 --(b1+bn2+relu, tf32)--> g_a2 NHWC
// MODE 1: g_a2    --(copy staged)-----> conv2 --(b2 + residual x)----> out NCHW
template <int MODE>
__global__ void __launch_bounds__(256, 2)
conv_kernel(const float* __restrict__ src,
            const float* __restrict__ w,
            const float* __restrict__ bias,
            const float* __restrict__ g1, const float* __restrict__ be1,
            const float* __restrict__ m1, const float* __restrict__ v1,
            const float* __restrict__ g2, const float* __restrict__ be2,
            const float* __restrict__ m2, const float* __restrict__ v2,
            const float* __restrict__ resid,
            float* __restrict__ dst)
{
    extern __shared__ float sm[];
    float* As  = sm;
    float* Bs  = sm + ANF;
    float* SS1 = sm + OFF_SS1;
    float* TT1 = sm + OFF_TT1;
    float* SS2 = sm + OFF_SS2;
    float* TT2 = sm + OFF_TT2;

    const int tid = threadIdx.x;
    const int x0  = blockIdx.x * 64;
    const int y0  = blockIdx.y * RROWS;
    const int b   = blockIdx.z;

    if (MODE == 0) {
        if (tid < 32) {
            float sc = g1[tid] * rsqrtf(v1[tid] + EPSV);
            SS1[tid] = sc;
            TT1[tid] = be1[tid] - m1[tid] * sc;
        } else if (tid < 64) {
            int c = tid - 32;
            float sc = g2[c] * rsqrtf(v2[c] + EPSV);
            SS2[c] = sc;
            TT2[c] = bias[c] * sc + (be2[c] - m2[c] * sc);
        }
        __syncthreads();
    }

    // ---- stage weights: Bs[((tap*4+q)*32+co)*8+pos] ----
    for (int i = tid; i < CH * CH * 9; i += 256) {
        int co  = i / 288;
        int rem = i - co * 288;
        int ci  = rem / 9;
        int tap = rem - ci * 9;
        int q   = ci >> 3;
        int c   = ci & 7;
        int pos = ((c & 3) << 1) | ((c >> 2) & 1);
        Bs[((tap * 4 + q) * 32 + co) * 8 + pos] = __uint_as_float(f2tf32(w[i]));
    }

    // ---- stage input rows (6 x 66 px x 32 ch) ----
    if (MODE == 0) {
        // from NCHW x with fused bn1+relu+tf32; channel-quad per pos-quad qq
        const float* xb0 = src + (size_t)b * CH * HW;
        for (int i = tid; i < 6 * 8 * 66; i += 256) {
            int s   = i / 528;
            int rem = i - s * 528;
            int qq  = rem / 66;
            int px  = rem - qq * 66;
            int yin = y0 - 1 + s;
            int gx  = x0 - 1 + px;
            int o   = (qq >> 1) << 3;
            int c0, c1, c2, c3;
            if (qq & 1) { c0 = o + 2; c1 = o + 6; c2 = o + 3; c3 = o + 7; }
            else        { c0 = o + 0; c1 = o + 4; c2 = o + 1; c3 = o + 5; }
            uint4 tv = make_uint4(0u, 0u, 0u, 0u);
            if ((unsigned)yin < (unsigned)HH && (unsigned)gx < (unsigned)WW) {
                const float* p = xb0 + (size_t)yin * WW + gx;
                tv.x = f2tf32(fmaxf(p[(size_t)c0 * HW] * SS1[c0] + TT1[c0], 0.f));
                tv.y = f2tf32(fmaxf(p[(size_t)c1 * HW] * SS1[c1] + TT1[c1], 0.f));
                tv.z = f2tf32(fmaxf(p[(size_t)c2 * HW] * SS1[c2] + TT1[c2], 0.f));
                tv.w = f2tf32(fmaxf(p[(size_t)c3 * HW] * SS1[c3] + TT1[c3], 0.f));
            }
            *(uint4*)(As + s * ASLOT + px * ASTRIDE + qq * 4) = tv;
        }
    } else {
        // from padded NHWC g_a2 (already permuted + tf32): pure float4 copy
        const float* srcb = src + (((size_t)b * PAD + y0) * PAD + x0) * CH;
        for (int i = tid; i < 6 * 528; i += 256) {
            int s = i / 528;
            int j = i - s * 528;
            float4 v = ((const float4*)(srcb + (size_t)s * PAD * CH))[j];
            int px = j >> 3;
            int qq = j & 7;
            *(float4*)(As + s * ASLOT + px * ASTRIDE + qq * 4) = v;
        }
    }
    __syncthreads();

    // ---- MMA mainloop ----
    const int lane = tid & 31;
    const int warp = tid >> 5;
    const int g    = lane >> 2;
    const int tig  = lane & 3;
    const int r    = warp >> 1;          // output row 0..3
    const int xh   = (warp & 1) * 32;    // half of the 64-px tile

    float C[2][4][4];
    #pragma unroll
    for (int mt = 0; mt < 2; mt++)
        #pragma unroll
        for (int n = 0; n < 4; n++)
            #pragma unroll
            for (int k = 0; k < 4; k++) C[mt][n][k] = 0.f;

    #pragma unroll 1
    for (int ky = 0; ky < 3; ky++) {
        #pragma unroll 1
        for (int kx = 0; kx < 3; kx++) {
            const int tap = ky * 3 + kx;
            uint32_t bq[4][4][2];
            const float* Bt = Bs + tap * 1024;
            #pragma unroll
            for (int q = 0; q < 4; q++)
                #pragma unroll
                for (int n = 0; n < 4; n++) {
                    float2 bb = *(const float2*)(Bt + (q * 32 + n * 8 + g) * 8 + 2 * tig);
                    bq[q][n][0] = __float_as_uint(bb.x);
                    bq[q][n][1] = __float_as_uint(bb.y);
                }
            const float* Arow = As + (r + ky) * ASLOT + kx * ASTRIDE;
            #pragma unroll
            for (int mt = 0; mt < 2; mt++) {
                const int xb = xh + mt * 16;
                #pragma unroll
                for (int q = 0; q < 4; q++) {
                    const float* ap = Arow + (xb + g) * ASTRIDE + q * 8 + 2 * tig;
                    float2 a01 = *(const float2*)ap;
                    float2 a23 = *(const float2*)(ap + 8 * ASTRIDE);
                    uint32_t a0 = __float_as_uint(a01.x);
                    uint32_t a2 = __float_as_uint(a01.y);
                    uint32_t a1 = __float_as_uint(a23.x);
                    uint32_t a3 = __float_as_uint(a23.y);
                    #pragma unroll
                    for (int n = 0; n < 4; n++)
                        mma_tf32(C[mt][n], a0, a1, a2, a3, bq[q][n][0], bq[q][n][1]);
                }
            }
        }
    }

    // ---- epilogue ----
    if (MODE == 0) {
        __syncthreads();                 // all MMA reads of As done; reuse as Os
        float* Os = sm;                  // [256 px][33]
        const int pr = r * 64;
        #pragma unroll
        for (int mt = 0; mt < 2; mt++) {
            const int xb = xh + mt * 16;
            #pragma unroll
            for (int n = 0; n < 4; n++) {
                const int co = n * 8 + 2 * tig;
                float s0 = SS2[co],     t0 = TT2[co];
                float s1 = SS2[co + 1], t1 = TT2[co + 1];
                int p0 = (pr + xb + g) * 33;
                int p1 = (pr + xb + g + 8) * 33;
                int cp0 = posidx(co), cp1 = posidx(co + 1);
                Os[p0 + cp0] = __uint_as_float(f2tf32(fmaxf(C[mt][n][0] * s0 + t0, 0.f)));
                Os[p0 + cp1] = __uint_as_float(f2tf32(fmaxf(C[mt][n][1] * s1 + t1, 0.f)));
                Os[p1 + cp0] = __uint_as_float(f2tf32(fmaxf(C[mt][n][2] * s0 + t0, 0.f)));
                Os[p1 + cp1] = __uint_as_float(f2tf32(fmaxf(C[mt][n][3] * s1 + t1, 0.f)));
            }
        }
        __syncthreads();
        // 4 rows * 64 px * 8 float4 = 2048 float4 total
        float* d0 = dst + (((size_t)b * PAD + (y0 + 1)) * PAD + (x0 + 1)) * CH;
        for (int i = tid; i < 2048; i += 256) {
            int rr  = i >> 9;
            int rem = i & 511;
            int pxl = rem >> 3;
            int f4  = rem & 7;
            const float* s = Os + (rr * 64 + pxl) * 33 + f4 * 4;
            float4 v = make_float4(s[0], s[1], s[2], s[3]);
            *(float4*)(d0 + (size_t)rr * PAD * CH + (size_t)pxl * CH + f4 * 4) = v;
        }
    } else {
        const int y = y0 + r;
        #pragma unroll
        for (int mt = 0; mt < 2; mt++) {
            const int xb = xh + mt * 16;
            #pragma unroll
            for (int n = 0; n < 4; n++) {
                const int co = n * 8 + 2 * tig;
                float bb0 = bias[co], bb1 = bias[co + 1];
                size_t o00 = (((size_t)b * CH + co)     * HH + y) * WW + (x0 + xb + g);
                size_t o01 = (((size_t)b * CH + co + 1) * HH + y) * WW + (x0 + xb + g);
                dst[o00]     = C[mt][n][0] + bb0 + resid[o00];
                dst[o01]     = C[mt][n][1] + bb1 + resid[o01];
                dst[o00 + 8] = C[mt][n][2] + bb0 + resid[o00 + 8];
                dst[o01 + 8] = C[mt][n][3] + bb1 + resid[o01 + 8];
            }
        }
    }
}

// ---- launch ----
extern "C" void kernel_launch(void* const* d_in, const int* in_sizes, int n_in,
                              void* d_out, int out_size)
{
    const float* x         = (const float*)d_in[0];
    const float* bn1_gamma = (const float*)d_in[1];
    const float* bn1_beta  = (const float*)d_in[2];
    const float* bn1_mean  = (const float*)d_in[3];
    const float* bn1_var   = (const float*)d_in[4];
    const float* w1        = (const float*)d_in[5];
    const float* b1        = (const float*)d_in[6];
    const float* bn2_gamma = (const float*)d_in[7];
    const float* bn2_beta  = (const float*)d_in[8];
    const float* bn2_mean  = (const float*)d_in[9];
    const float* bn2_var   = (const float*)d_in[10];
    const float* w2        = (const float*)d_in[11];
    const float* b2        = (const float*)d_in[12];
    float* out = (float*)d_out;

    void* a2p = nullptr;
    cudaGetSymbolAddress(&a2p, g_a2);
    float* a2 = (float*)a2p;

    cudaFuncSetAttribute(conv_kernel<0>, cudaFuncAttributeMaxDynamicSharedMemorySize, SMEMB);
    cudaFuncSetAttribute(conv_kernel<1>, cudaFuncAttributeMaxDynamicSharedMemorySize, SMEMB);

    border_kernel<<<(BATCH * 516 * 8 + 255) / 256, 256>>>();

    dim3 grid(2, HH / RROWS, BATCH);   // (2, 32, 64)

    conv_kernel<0><<<grid, 256, SMEMB>>>(x, w1, b1,
                                         bn1_gamma, bn1_beta, bn1_mean, bn1_var,
                                         bn2_gamma, bn2_beta, bn2_mean, bn2_var,
                                         nullptr, a2);

    conv_kernel<1><<<grid, 256, SMEMB>>>(a2, w2, b2,
                                         nullptr, nullptr, nullptr, nullptr,
                                         nullptr, nullptr, nullptr, nullptr,
                                         x, out);
}

// round 7
// speedup vs baseline: 8.1838x; 1.4858x over previous
#include <cuda_runtime.h>
#include <cuda_fp16.h>
#include <cstdint>
#include <math.h>

#define BATCH 64
#define CH    32
#define HH    128
#define WW    128
#define PAD   130
#define EPSV  1e-5f
#define RROWS 4
#define HW    (HH * WW)

// conv1 activations: padded NHWC, half2 channel-pairs in permuted positions; borders zero
// per pixel: 16 u32 (=32 fp16 channels)
__device__ uint32_t g_a2[(size_t)BATCH * PAD * PAD * 16];

// pair permutation within an 8-pair chunk: pair p stored at position 2*(p&3) + (p>>2)
__device__ __host__ __forceinline__ int pos8(int p) {
    return ((p & 3) << 1) | ((p >> 2) & 1);
}

__device__ __forceinline__ uint32_t h2_as_u32(__half2 h) {
    return *reinterpret_cast<uint32_t*>(&h);
}

__device__ __forceinline__ void mma_f16(float c[4],
                                        uint32_t a0, uint32_t a1, uint32_t a2, uint32_t a3,
                                        uint32_t b0, uint32_t b1) {
    asm volatile(
        "mma.sync.aligned.m16n8k16.row.col.f32.f16.f16.f32 "
        "{%0,%1,%2,%3}, {%4,%5,%6,%7}, {%8,%9}, {%0,%1,%2,%3};"
        : "+f"(c[0]), "+f"(c[1]), "+f"(c[2]), "+f"(c[3])
        : "r"(a0), "r"(a1), "r"(a2), "r"(a3), "r"(b0), "r"(b1));
}

// ---- smem layout (u32 units) ----
#define ASTRIDE 24                    // 16 data + 8 pad per pixel
#define ASLOT   (66 * ASTRIDE)        // 1584
#define ANF     (6 * ASLOT)           // 9504
#define BNF     (9 * 2 * 32 * 8)      // 4608  [tap][q][co][8]
#define OFF_SS1 (ANF + BNF)           // 14112
#define OFF_TT1 (OFF_SS1 + 32)
#define OFF_SS2 (OFF_TT1 + 32)
#define OFF_TT2 (OFF_SS2 + 32)
#define SNF     (OFF_TT2 + 32)        // 14240 u32
#define SMEMB   (SNF * 4)             // 56960 B
// MODE0 epilogue staging reuses As region: 256 px * 20 u32 = 5120 u32

// zero borders of g_a2 (516 border px per batch, 4 uint4 each)
__global__ void border_kernel() {
    int i = blockIdx.x * 256 + threadIdx.x;     // over 64*516*4
    if (i >= BATCH * 516 * 4) return;
    int f4 = i & 3;
    int t  = i >> 2;
    int p  = t % 516;
    int b  = t / 516;
    int yp, xp;
    if      (p < 130) { yp = 0;       xp = p; }
    else if (p < 260) { yp = PAD - 1; xp = p - 130; }
    else if (p < 388) { yp = p - 259; xp = 0; }
    else              { yp = p - 387; xp = PAD - 1; }
    uint4* d = (uint4*)(g_a2 + (((size_t)b * PAD + yp) * PAD + xp) * 16);
    d[f4] = make_uint4(0u, 0u, 0u, 0u);
}

// MODE 0: x NCHW --(bn1+relu+fp16 staged)--> conv1 --(b1+bn2+relu, fp16)--> g_a2
// MODE 1: g_a2   --(copy staged)----------> conv2 --(b2 + residual x)----> out NCHW
template <int MODE>
__global__ void __launch_bounds__(256, 2)
conv_kernel(const void* __restrict__ srcv,
            const float* __restrict__ w,
            const float* __restrict__ bias,
            const float* __restrict__ g1, const float* __restrict__ be1,
            const float* __restrict__ m1, const float* __restrict__ v1,
            const float* __restrict__ g2, const float* __restrict__ be2,
            const float* __restrict__ m2, const float* __restrict__ v2,
            const float* __restrict__ resid,
            void* __restrict__ dstv)
{
    extern __shared__ uint32_t sm[];
    uint32_t* As  = sm;
    uint32_t* Bs  = sm + ANF;
    float* SS1 = (float*)(sm + OFF_SS1);
    float* TT1 = (float*)(sm + OFF_TT1);
    float* SS2 = (float*)(sm + OFF_SS2);
    float* TT2 = (float*)(sm + OFF_TT2);

    const int tid = threadIdx.x;
    const int x0  = blockIdx.x * 64;
    const int y0  = blockIdx.y * RROWS;
    const int b   = blockIdx.z;

    if (MODE == 0) {
        if (tid < 32) {
            float sc = g1[tid] * rsqrtf(v1[tid] + EPSV);
            SS1[tid] = sc;
            TT1[tid] = be1[tid] - m1[tid] * sc;
        } else if (tid < 64) {
            int c = tid - 32;
            float sc = g2[c] * rsqrtf(v2[c] + EPSV);
            SS2[c] = sc;
            TT2[c] = bias[c] * sc + (be2[c] - m2[c] * sc);
        }
        __syncthreads();
    }

    // ---- stage weights as fp16: Bs[((tap*2+q)*32+co)*8 + pos], half idx *2 + (ci&1) ----
    {
        __half* Bh = (__half*)Bs;
        for (int i = tid; i < CH * CH * 9; i += 256) {
            int co  = i / 288;
            int rem = i - co * 288;
            int ci  = rem / 9;
            int tap = rem - ci * 9;
            int q   = ci >> 4;
            int pl  = (ci >> 1) & 7;
            int idx = ((tap * 2 + q) * 32 + co) * 8 + pos8(pl);
            Bh[idx * 2 + (ci & 1)] = __float2half_rn(w[i]);
        }
    }

    // ---- stage 6 input rows x 66 px x 16 u32 ----
    if (MODE == 0) {
        const float* xb0 = (const float*)srcv + (size_t)b * CH * HW;
        for (int i = tid; i < 6 * 16 * 66; i += 256) {
            int s   = i / 1056;
            int rem = i - s * 1056;
            int j   = rem / 66;              // storage position 0..15
            int px  = rem - j * 66;
            int yin = y0 - 1 + s;
            int gx  = x0 - 1 + px;
            int q   = j >> 3;
            int jj  = j & 7;
            int pl  = ((jj & 1) << 2) | (jj >> 1);
            int c0  = (q * 8 + pl) * 2;
            int c1  = c0 + 1;
            uint32_t val = 0u;
            if ((unsigned)yin < (unsigned)HH && (unsigned)gx < (unsigned)WW) {
                const float* p = xb0 + (size_t)yin * WW + gx;
                float v0 = fmaxf(p[(size_t)c0 * HW] * SS1[c0] + TT1[c0], 0.f);
                float v1 = fmaxf(p[(size_t)c1 * HW] * SS1[c1] + TT1[c1], 0.f);
                val = h2_as_u32(__floats2half2_rn(v0, v1));
            }
            As[s * ASLOT + px * ASTRIDE + j] = val;
        }
    } else {
        const uint32_t* srcb = (const uint32_t*)srcv + (((size_t)b * PAD + y0) * PAD + x0) * 16;
        for (int i = tid; i < 6 * 66 * 4; i += 256) {      // uint4 granularity
            int s = i / 264;
            int j = i - s * 264;
            int px = j >> 2;
            int f4 = j & 3;
            uint4 v = ((const uint4*)(srcb + (size_t)s * PAD * 16))[px * 4 + f4];
            *(uint4*)(As + s * ASLOT + px * ASTRIDE + f4 * 4) = v;
        }
    }
    __syncthreads();

    // ---- MMA mainloop ----
    const int lane = tid & 31;
    const int warp = tid >> 5;
    const int g    = lane >> 2;
    const int tig  = lane & 3;
    const int r    = warp >> 1;          // output row 0..3
    const int xh   = (warp & 1) * 32;

    float C[2][4][4];
    #pragma unroll
    for (int mt = 0; mt < 2; mt++)
        #pragma unroll
        for (int n = 0; n < 4; n++)
            #pragma unroll
            for (int k = 0; k < 4; k++) C[mt][n][k] = 0.f;

    #pragma unroll 1
    for (int ky = 0; ky < 3; ky++) {
        #pragma unroll 1
        for (int kx = 0; kx < 3; kx++) {
            const int tap = ky * 3 + kx;
            uint32_t bq[2][4][2];
            #pragma unroll
            for (int q = 0; q < 2; q++)
                #pragma unroll
                for (int n = 0; n < 4; n++) {
                    uint2 bb = *(const uint2*)(Bs + (((tap * 2 + q) * 32) + n * 8 + g) * 8 + 2 * tig);
                    bq[q][n][0] = bb.x;
                    bq[q][n][1] = bb.y;
                }
            const uint32_t* Arow = As + (r + ky) * ASLOT + kx * ASTRIDE;
            #pragma unroll
            for (int mt = 0; mt < 2; mt++) {
                const int xb = xh + mt * 16;
                #pragma unroll
                for (int q = 0; q < 2; q++) {
                    const uint32_t* ap = Arow + (xb + g) * ASTRIDE + q * 8 + 2 * tig;
                    uint2 a02 = *(const uint2*)ap;                       // pixel xb+g
                    uint2 a13 = *(const uint2*)(ap + 8 * ASTRIDE);       // pixel xb+g+8
                    #pragma unroll
                    for (int n = 0; n < 4; n++)
                        mma_f16(C[mt][n], a02.x, a13.x, a02.y, a13.y,
                                bq[q][n][0], bq[q][n][1]);
                }
            }
        }
    }

    // ---- epilogue ----
    if (MODE == 0) {
        __syncthreads();
        uint32_t* Os = sm;                // [256 px][20 u32]
        const int pr = r * 64;
        #pragma unroll
        for (int mt = 0; mt < 2; mt++) {
            const int xb = xh + mt * 16;
            #pragma unroll
            for (int n = 0; n < 4; n++) {
                const int co = n * 8 + 2 * tig;
                const int p  = n * 4 + tig;                       // pair index
                const int pos = ((p >> 3) << 3) + pos8(p & 7);
                float s0 = SS2[co],     t0 = TT2[co];
                float s1 = SS2[co + 1], t1 = TT2[co + 1];
                float v0 = fmaxf(C[mt][n][0] * s0 + t0, 0.f);
                float v1 = fmaxf(C[mt][n][1] * s1 + t1, 0.f);
                float v2 = fmaxf(C[mt][n][2] * s0 + t0, 0.f);
                float v3 = fmaxf(C[mt][n][3] * s1 + t1, 0.f);
                Os[(pr + xb + g) * 20 + pos]     = h2_as_u32(__floats2half2_rn(v0, v1));
                Os[(pr + xb + g + 8) * 20 + pos] = h2_as_u32(__floats2half2_rn(v2, v3));
            }
        }
        __syncthreads();
        // 4 rows * 64 px * 4 uint4 = 1024 uint4, coalesced
        uint32_t* d0 = (uint32_t*)dstv + (((size_t)b * PAD + (y0 + 1)) * PAD + (x0 + 1)) * 16;
        for (int i = tid; i < 1024; i += 256) {
            int rr  = i >> 8;
            int rem = i & 255;
            int pxl = rem >> 2;
            int f4  = rem & 3;
            uint4 v = *(const uint4*)(Os + (rr * 64 + pxl) * 20 + f4 * 4);
            *(uint4*)(d0 + (size_t)rr * PAD * 16 + (size_t)pxl * 16 + f4 * 4) = v;
        }
    } else {
        float* dst = (float*)dstv;
        const int y = y0 + r;
        #pragma unroll
        for (int mt = 0; mt < 2; mt++) {
            const int xb = xh + mt * 16;
            #pragma unroll
            for (int n = 0; n < 4; n++) {
                const int co = n * 8 + 2 * tig;
                float bb0 = bias[co], bb1 = bias[co + 1];
                size_t o00 = (((size_t)b * CH + co)     * HH + y) * WW + (x0 + xb + g);
                size_t o01 = (((size_t)b * CH + co + 1) * HH + y) * WW + (x0 + xb + g);
                dst[o00]     = C[mt][n][0] + bb0 + resid[o00];
                dst[o01]     = C[mt][n][1] + bb1 + resid[o01];
                dst[o00 + 8] = C[mt][n][2] + bb0 + resid[o00 + 8];
                dst[o01 + 8] = C[mt][n][3] + bb1 + resid[o01 + 8];
            }
        }
    }
}

// ---- launch ----
extern "C" void kernel_launch(void* const* d_in, const int* in_sizes, int n_in,
                              void* d_out, int out_size)
{
    const float* x         = (const float*)d_in[0];
    const float* bn1_gamma = (const float*)d_in[1];
    const float* bn1_beta  = (const float*)d_in[2];
    const float* bn1_mean  = (const float*)d_in[3];
    const float* bn1_var   = (const float*)d_in[4];
    const float* w1        = (const float*)d_in[5];
    const float* b1        = (const float*)d_in[6];
    const float* bn2_gamma = (const float*)d_in[7];
    const float* bn2_beta  = (const float*)d_in[8];
    const float* bn2_mean  = (const float*)d_in[9];
    const float* bn2_var   = (const float*)d_in[10];
    const float* w2        = (const float*)d_in[11];
    const float* b2        = (const float*)d_in[12];
    float* out = (float*)d_out;

    void* a2p = nullptr;
    cudaGetSymbolAddress(&a2p, g_a2);

    cudaFuncSetAttribute(conv_kernel<0>, cudaFuncAttributeMaxDynamicSharedMemorySize, SMEMB);
    cudaFuncSetAttribute(conv_kernel<1>, cudaFuncAttributeMaxDynamicSharedMemorySize, SMEMB);

    border_kernel<<<(BATCH * 516 * 4 + 255) / 256, 256>>>();

    dim3 grid(2, HH / RROWS, BATCH);   // (2, 32, 64)

    conv_kernel<0><<<grid, 256, SMEMB>>>(x, w1, b1,
                                         bn1_gamma, bn1_beta, bn1_mean, bn1_var,
                                         bn2_gamma, bn2_beta, bn2_mean, bn2_var,
                                         nullptr, a2p);

    conv_kernel<1><<<grid, 256, SMEMB>>>(a2p, w2, b2,
                                         nullptr, nullptr, nullptr, nullptr,
                                         nullptr, nullptr, nullptr, nullptr,
                                         x, out);
}